// round 4
// baseline (speedup 1.0000x reference)
#include <cuda_runtime.h>
#include <cuda_bf16.h>

#define NN 20000
#define NE 100000
#define ND 128
#define ED 128
#define EIN 291
#define HH 64
#define EPB 4

// Scratch (device globals; no allocation allowed)
__device__ float g_nf0[NN * ND];
__device__ float g_nfA[NN * ND];
__device__ float g_nfB[NN * ND];
__device__ float g_ef0[NE * ED];
__device__ float g_ef [NE * ED];

// ---------------------------------------------------------------------------
// Node embedding: nf0 = lin(relu(lin(x, new0)), new1)   [N,128]
// ---------------------------------------------------------------------------
__global__ void node_embed_kernel(const float* __restrict__ x,
                                  const float* __restrict__ w0, const float* __restrict__ b0,
                                  const float* __restrict__ w1, const float* __restrict__ b1)
{
    __shared__ float s_x[EPB][ND];
    __shared__ float s_h[EPB][ND];
    const int t = threadIdx.x;
    const int nb = blockIdx.x * EPB;

    #pragma unroll
    for (int r = 0; r < EPB; r++) s_x[r][t] = x[(nb + r) * ND + t];
    __syncthreads();

    float acc[EPB];
    {
        const float b = b0[t];
        #pragma unroll
        for (int r = 0; r < EPB; r++) acc[r] = b;
        #pragma unroll 4
        for (int k = 0; k < ND; k++) {
            const float w = w0[k * ND + t];
            #pragma unroll
            for (int r = 0; r < EPB; r++) acc[r] += s_x[r][k] * w;
        }
        #pragma unroll
        for (int r = 0; r < EPB; r++) s_h[r][t] = fmaxf(acc[r], 0.f);
    }
    __syncthreads();
    {
        const float b = b1[t];
        #pragma unroll
        for (int r = 0; r < EPB; r++) acc[r] = b;
        #pragma unroll 4
        for (int k = 0; k < ND; k++) {
            const float w = w1[k * ND + t];
            #pragma unroll
            for (int r = 0; r < EPB; r++) acc[r] += s_h[r][k] * w;
        }
        #pragma unroll
        for (int r = 0; r < EPB; r++) g_nf0[(nb + r) * ND + t] = acc[r];
    }
}

// ---------------------------------------------------------------------------
// Edge embedding: ef0 = lin(relu(lin(edge_attr, eew0)), eew1)   [E,128]
// ---------------------------------------------------------------------------
__global__ void edge_embed_kernel(const float* __restrict__ ea,
                                  const float* __restrict__ w0, const float* __restrict__ b0,
                                  const float* __restrict__ w1, const float* __restrict__ b1)
{
    __shared__ float s_in[EPB][EIN + 1];
    __shared__ float s_part[128][EPB + 1];
    __shared__ float s_h[EPB][HH];
    const int t = threadIdx.x;
    const int eb = blockIdx.x * EPB;

    #pragma unroll
    for (int r = 0; r < EPB; r++) {
        const float* row = ea + (size_t)(eb + r) * EIN;
        for (int k = t; k < EIN; k += 128) s_in[r][k] = row[k];
    }
    __syncthreads();

    const int c = t & 63, half = t >> 6;
    const int ks = half ? 146 : 0;
    const int ke = half ? EIN : 146;
    float acc[EPB] = {0.f, 0.f, 0.f, 0.f};
    for (int k = ks; k < ke; k++) {
        const float w = w0[k * HH + c];
        #pragma unroll
        for (int r = 0; r < EPB; r++) acc[r] += s_in[r][k] * w;
    }
    #pragma unroll
    for (int r = 0; r < EPB; r++) s_part[t][r] = acc[r];
    __syncthreads();

    if (t < HH) {
        const float b = b0[t];
        #pragma unroll
        for (int r = 0; r < EPB; r++)
            s_h[r][t] = fmaxf(s_part[t][r] + s_part[t + 64][r] + b, 0.f);
    }
    __syncthreads();

    {
        const float b = b1[t];
        float a2[EPB];
        #pragma unroll
        for (int r = 0; r < EPB; r++) a2[r] = b;
        #pragma unroll 4
        for (int k = 0; k < HH; k++) {
            const float w = w1[k * ED + t];
            #pragma unroll
            for (int r = 0; r < EPB; r++) a2[r] += s_h[r][k] * w;
        }
        #pragma unroll
        for (int r = 0; r < EPB; r++) {
            const int e = eb + r;
            g_ef0[e * ED + t] = a2[r];
            g_ef [e * ED + t] = a2[r];
        }
    }
}

// ---------------------------------------------------------------------------
// Zero target nf accumulation buffer (sel: 0 -> g_nfA, 1 -> g_nfB)
// ---------------------------------------------------------------------------
__global__ void zero_nf_kernel(int sel)
{
    float* p = sel ? g_nfB : g_nfA;
    const int i = blockIdx.x * blockDim.x + threadIdx.x;
    if (i < NN * ND) p[i] = 0.f;
}

// ---------------------------------------------------------------------------
// One message-passing step.
//   phase selects the ping-pong buffers:
//     phase 0: in g_nf0 out g_nfA
//     phase 1: in g_nfA out g_nfB
//     phase 2: in g_nfB out g_nfA
//     phase 3: in g_nfA out g_nfB (msg skipped: result unused)
// ---------------------------------------------------------------------------
__global__ void mpn_step_kernel(const int* __restrict__ ei,
                                const float* __restrict__ mew0, const float* __restrict__ meb0,
                                const float* __restrict__ mew1, const float* __restrict__ meb1,
                                const float* __restrict__ mnw0, const float* __restrict__ mnb0,
                                int phase, int compute_msg)
{
    __shared__ float s_in[EPB][768];
    __shared__ float s_part[128][EPB + 1];
    __shared__ float s_h[EPB][HH];
    __shared__ float s_ef[EPB][ED];
    __shared__ int   s_dst[EPB];

    const float* __restrict__ nf_in =
        (phase == 0) ? g_nf0 : ((phase & 1) ? g_nfA : g_nfB);
    float* __restrict__ nf_out = (phase & 1) ? g_nfB : g_nfA;

    const int t = threadIdx.x;
    const int eb = blockIdx.x * EPB;

    #pragma unroll
    for (int r = 0; r < EPB; r++) {
        const int e = eb + r;
        const int j = ei[e];        // source
        const int i = ei[NE + e];   // target
        if (t == 0) s_dst[r] = i;
        s_in[r][t]       = g_nf0 [i * ND + t];
        s_in[r][128 + t] = nf_in [i * ND + t];
        s_in[r][256 + t] = g_nf0 [j * ND + t];
        s_in[r][384 + t] = nf_in [j * ND + t];
        s_in[r][512 + t] = g_ef0 [e * ED + t];
        s_in[r][640 + t] = g_ef  [e * ED + t];
    }
    __syncthreads();

    // Phase 1: h = relu([x_i | x_j | efc] @ mew0 + meb0), 64 outputs,
    // two threads cooperate on each output (split k-range 768 -> 2x384).
    {
        const int c = t & 63, half = t >> 6;
        const int k0 = half * 384;
        float acc[EPB] = {0.f, 0.f, 0.f, 0.f};
        #pragma unroll 4
        for (int kk = 0; kk < 384; kk++) {
            const int k = k0 + kk;
            const float w = mew0[k * HH + c];
            #pragma unroll
            for (int r = 0; r < EPB; r++) acc[r] += s_in[r][k] * w;
        }
        #pragma unroll
        for (int r = 0; r < EPB; r++) s_part[t][r] = acc[r];
    }
    __syncthreads();
    if (t < HH) {
        const float b = meb0[t];
        #pragma unroll
        for (int r = 0; r < EPB; r++)
            s_h[r][t] = fmaxf(s_part[t][r] + s_part[t + 64][r] + b, 0.f);
    }
    __syncthreads();

    // Phase 2: ef_new = relu(h @ mew1 + meb1)
    {
        const float b = meb1[t];
        float a2[EPB];
        #pragma unroll
        for (int r = 0; r < EPB; r++) a2[r] = b;
        #pragma unroll 4
        for (int k = 0; k < HH; k++) {
            const float w = mew1[k * ED + t];
            #pragma unroll
            for (int r = 0; r < EPB; r++) a2[r] += s_h[r][k] * w;
        }
        #pragma unroll
        for (int r = 0; r < EPB; r++) {
            const float v = fmaxf(a2[r], 0.f);
            s_ef[r][t] = v;
            g_ef[(eb + r) * ED + t] = v;
        }
    }

    if (!compute_msg) return;
    __syncthreads();

    // Phase 3: msg = relu([x_i | ef_new] @ mnw0 + mnb0); atomic scatter-add.
    {
        const float b = mnb0[t];
        float m[EPB];
        #pragma unroll
        for (int r = 0; r < EPB; r++) m[r] = b;
        #pragma unroll 4
        for (int k = 0; k < 256; k++) {
            const float w = mnw0[k * ND + t];
            #pragma unroll
            for (int r = 0; r < EPB; r++) m[r] += s_in[r][k] * w;
        }
        #pragma unroll 4
        for (int k = 0; k < 128; k++) {
            const float w = mnw0[(256 + k) * ND + t];
            #pragma unroll
            for (int r = 0; r < EPB; r++) m[r] += s_ef[r][k] * w;
        }
        #pragma unroll
        for (int r = 0; r < EPB; r++)
            atomicAdd(&nf_out[s_dst[r] * ND + t], fmaxf(m[r], 0.f));
    }
}

// ---------------------------------------------------------------------------
// Classifier: out = lin(relu(lin(relu(lin(ef, cw0)), cw1)), cw2)  [E,1]
// ---------------------------------------------------------------------------
__global__ void classify_kernel(float* __restrict__ out,
                                const float* __restrict__ cw0, const float* __restrict__ cb0,
                                const float* __restrict__ cw1, const float* __restrict__ cb1,
                                const float* __restrict__ cw2, const float* __restrict__ cb2)
{
    __shared__ float s_ef[EPB][ED];
    __shared__ float s_h0[EPB][64];
    __shared__ float s_h1[EPB][32];
    const int t = threadIdx.x;
    const int eb = blockIdx.x * EPB;

    #pragma unroll
    for (int r = 0; r < EPB; r++) s_ef[r][t] = g_ef[(eb + r) * ED + t];
    __syncthreads();

    if (t < 64) {
        const float b = cb0[t];
        float a[EPB];
        #pragma unroll
        for (int r = 0; r < EPB; r++) a[r] = b;
        #pragma unroll 4
        for (int k = 0; k < 128; k++) {
            const float w = cw0[k * 64 + t];
            #pragma unroll
            for (int r = 0; r < EPB; r++) a[r] += s_ef[r][k] * w;
        }
        #pragma unroll
        for (int r = 0; r < EPB; r++) s_h0[r][t] = fmaxf(a[r], 0.f);
    }
    __syncthreads();

    if (t < 32) {
        const float b = cb1[t];
        float a[EPB];
        #pragma unroll
        for (int r = 0; r < EPB; r++) a[r] = b;
        #pragma unroll 4
        for (int k = 0; k < 64; k++) {
            const float w = cw1[k * 32 + t];
            #pragma unroll
            for (int r = 0; r < EPB; r++) a[r] += s_h0[r][k] * w;
        }
        #pragma unroll
        for (int r = 0; r < EPB; r++) s_h1[r][t] = fmaxf(a[r], 0.f);
    }
    __syncthreads();

    if (t < 32) {
        const float w2 = cw2[t];
        #pragma unroll
        for (int r = 0; r < EPB; r++) {
            float v = s_h1[r][t] * w2;
            #pragma unroll
            for (int off = 16; off > 0; off >>= 1)
                v += __shfl_down_sync(0xFFFFFFFFu, v, off);
            if (t == 0) out[eb + r] = v + cb2[0];
        }
    }
}

// ---------------------------------------------------------------------------
extern "C" void kernel_launch(void* const* d_in, const int* in_sizes, int n_in,
                              void* d_out, int out_size)
{
    const float* x    = (const float*)d_in[0];
    const float* ea   = (const float*)d_in[1];
    const int*   ei   = (const int*)  d_in[2];
    const float* new0 = (const float*)d_in[3];
    const float* neb0 = (const float*)d_in[4];
    const float* new1 = (const float*)d_in[5];
    const float* neb1 = (const float*)d_in[6];
    const float* eew0 = (const float*)d_in[7];
    const float* eeb0 = (const float*)d_in[8];
    const float* eew1 = (const float*)d_in[9];
    const float* eeb1 = (const float*)d_in[10];
    const float* mew0 = (const float*)d_in[11];
    const float* meb0 = (const float*)d_in[12];
    const float* mew1 = (const float*)d_in[13];
    const float* meb1 = (const float*)d_in[14];
    const float* mnw0 = (const float*)d_in[15];
    const float* mnb0 = (const float*)d_in[16];
    const float* cw0  = (const float*)d_in[17];
    const float* cb0  = (const float*)d_in[18];
    const float* cw1  = (const float*)d_in[19];
    const float* cb1  = (const float*)d_in[20];
    const float* cw2  = (const float*)d_in[21];
    const float* cb2  = (const float*)d_in[22];
    float* out = (float*)d_out;

    node_embed_kernel<<<NN / EPB, 128>>>(x, new0, neb0, new1, neb1);
    edge_embed_kernel<<<NE / EPB, 128>>>(ea, eew0, eeb0, eew1, eeb1);

    const int zgrid = (NN * ND + 255) / 256;
    // step 0: in nf0, out A
    zero_nf_kernel<<<zgrid, 256>>>(0);
    mpn_step_kernel<<<NE / EPB, 128>>>(ei, mew0, meb0, mew1, meb1, mnw0, mnb0, 0, 1);
    // step 1: in A, out B
    zero_nf_kernel<<<zgrid, 256>>>(1);
    mpn_step_kernel<<<NE / EPB, 128>>>(ei, mew0, meb0, mew1, meb1, mnw0, mnb0, 1, 1);
    // step 2: in B, out A
    zero_nf_kernel<<<zgrid, 256>>>(0);
    mpn_step_kernel<<<NE / EPB, 128>>>(ei, mew0, meb0, mew1, meb1, mnw0, mnb0, 2, 1);
    // step 3: in A; final nf never consumed -> skip message/aggregation
    mpn_step_kernel<<<NE / EPB, 128>>>(ei, mew0, meb0, mew1, meb1, mnw0, mnb0, 3, 0);

    classify_kernel<<<NE / EPB, 128>>>(out, cw0, cb0, cw1, cb1, cw2, cb2);
}

// round 6
// speedup vs baseline: 1.0727x; 1.0727x over previous
#include <cuda_runtime.h>
#include <cuda_bf16.h>

#define NN 20000
#define NE 100000
#define ND 128
#define ED 128
#define EIN 291
#define HH 64
#define EPB 8

// Scratch (device globals; no allocation allowed)
__device__ float g_nf0[NN * ND];
__device__ float g_nfA[NN * ND];
__device__ float g_nfB[NN * ND];
__device__ float g_ef0[NE * ED];
__device__ float g_ef [NE * ED];

// ---------------------------------------------------------------------------
// Node embedding: nf0 = lin(relu(lin(x, new0)), new1)   [N,128]
// ---------------------------------------------------------------------------
__global__ void node_embed_kernel(const float* __restrict__ x,
                                  const float* __restrict__ w0, const float* __restrict__ b0,
                                  const float* __restrict__ w1, const float* __restrict__ b1)
{
    __shared__ float s_x[EPB][ND];
    __shared__ float s_h[EPB][ND];
    const int t = threadIdx.x;
    const int nb = blockIdx.x * EPB;

    #pragma unroll
    for (int r = 0; r < EPB; r++) s_x[r][t] = x[(nb + r) * ND + t];
    __syncthreads();

    float acc[EPB];
    {
        const float b = b0[t];
        #pragma unroll
        for (int r = 0; r < EPB; r++) acc[r] = b;
        #pragma unroll 4
        for (int k = 0; k < ND; k += 4) {
            float4 w4;
            w4.x = w0[(k + 0) * ND + t];
            w4.y = w0[(k + 1) * ND + t];
            w4.z = w0[(k + 2) * ND + t];
            w4.w = w0[(k + 3) * ND + t];
            #pragma unroll
            for (int r = 0; r < EPB; r++) {
                const float4 v = *(const float4*)&s_x[r][k];
                acc[r] += v.x * w4.x + v.y * w4.y + v.z * w4.z + v.w * w4.w;
            }
        }
        #pragma unroll
        for (int r = 0; r < EPB; r++) s_h[r][t] = fmaxf(acc[r], 0.f);
    }
    __syncthreads();
    {
        const float b = b1[t];
        #pragma unroll
        for (int r = 0; r < EPB; r++) acc[r] = b;
        #pragma unroll 4
        for (int k = 0; k < ND; k += 4) {
            float4 w4;
            w4.x = w1[(k + 0) * ND + t];
            w4.y = w1[(k + 1) * ND + t];
            w4.z = w1[(k + 2) * ND + t];
            w4.w = w1[(k + 3) * ND + t];
            #pragma unroll
            for (int r = 0; r < EPB; r++) {
                const float4 v = *(const float4*)&s_h[r][k];
                acc[r] += v.x * w4.x + v.y * w4.y + v.z * w4.z + v.w * w4.w;
            }
        }
        #pragma unroll
        for (int r = 0; r < EPB; r++) g_nf0[(nb + r) * ND + t] = acc[r];
    }
}

// ---------------------------------------------------------------------------
// Edge embedding: ef0 = lin(relu(lin(edge_attr, eew0)), eew1)   [E,128]
// ---------------------------------------------------------------------------
__global__ void edge_embed_kernel(const float* __restrict__ ea,
                                  const float* __restrict__ w0, const float* __restrict__ b0,
                                  const float* __restrict__ w1, const float* __restrict__ b1)
{
    __shared__ float s_in[EPB][EIN + 1];
    __shared__ float s_part[128][EPB + 1];
    __shared__ float s_h[EPB][HH];
    const int t = threadIdx.x;
    const int eb = blockIdx.x * EPB;

    #pragma unroll
    for (int r = 0; r < EPB; r++) {
        const float* row = ea + (size_t)(eb + r) * EIN;
        for (int k = t; k < EIN; k += 128) s_in[r][k] = row[k];
    }
    __syncthreads();

    const int c = t & 63, half = t >> 6;
    const int ks = half ? 146 : 0;
    const int ke = half ? EIN : 146;
    float acc[EPB];
    #pragma unroll
    for (int r = 0; r < EPB; r++) acc[r] = 0.f;
    for (int k = ks; k < ke; k++) {
        const float w = w0[k * HH + c];
        #pragma unroll
        for (int r = 0; r < EPB; r++) acc[r] += s_in[r][k] * w;
    }
    #pragma unroll
    for (int r = 0; r < EPB; r++) s_part[t][r] = acc[r];
    __syncthreads();

    if (t < HH) {
        const float b = b0[t];
        #pragma unroll
        for (int r = 0; r < EPB; r++)
            s_h[r][t] = fmaxf(s_part[t][r] + s_part[t + 64][r] + b, 0.f);
    }
    __syncthreads();

    {
        const float b = b1[t];
        float a2[EPB];
        #pragma unroll
        for (int r = 0; r < EPB; r++) a2[r] = b;
        #pragma unroll 4
        for (int k = 0; k < HH; k += 4) {
            float4 w4;
            w4.x = w1[(k + 0) * ED + t];
            w4.y = w1[(k + 1) * ED + t];
            w4.z = w1[(k + 2) * ED + t];
            w4.w = w1[(k + 3) * ED + t];
            #pragma unroll
            for (int r = 0; r < EPB; r++) {
                const float4 v = *(const float4*)&s_h[r][k];
                a2[r] += v.x * w4.x + v.y * w4.y + v.z * w4.z + v.w * w4.w;
            }
        }
        #pragma unroll
        for (int r = 0; r < EPB; r++) {
            const int e = eb + r;
            g_ef0[e * ED + t] = a2[r];
            g_ef [e * ED + t] = a2[r];
        }
    }
}

// ---------------------------------------------------------------------------
// Zero target nf accumulation buffer (sel: 0 -> g_nfA, 1 -> g_nfB)
// ---------------------------------------------------------------------------
__global__ void zero_nf_kernel(int sel)
{
    float* p = sel ? g_nfB : g_nfA;
    const int i = blockIdx.x * blockDim.x + threadIdx.x;
    if (i < NN * ND) p[i] = 0.f;
}

// ---------------------------------------------------------------------------
// One message-passing step.
//   phase selects the ping-pong buffers:
//     phase 0: in g_nf0 out g_nfA
//     phase 1: in g_nfA out g_nfB
//     phase 2: in g_nfB out g_nfA
//     phase 3: in g_nfA (msg skipped: result unused)
// ---------------------------------------------------------------------------
__global__ void mpn_step_kernel(const int* __restrict__ ei,
                                const float* __restrict__ mew0, const float* __restrict__ meb0,
                                const float* __restrict__ mew1, const float* __restrict__ meb1,
                                const float* __restrict__ mnw0, const float* __restrict__ mnb0,
                                int phase, int compute_msg)
{
    __shared__ float s_in[EPB][768];
    __shared__ float s_part[128][EPB + 1];
    __shared__ float s_h[EPB][HH];
    __shared__ float s_ef[EPB][ED];
    __shared__ int   s_dst[EPB];

    const float* __restrict__ nf_in =
        (phase == 0) ? g_nf0 : ((phase & 1) ? g_nfA : g_nfB);
    float* __restrict__ nf_out = (phase & 1) ? g_nfB : g_nfA;

    const int t = threadIdx.x;
    const int eb = blockIdx.x * EPB;

    #pragma unroll
    for (int r = 0; r < EPB; r++) {
        const int e = eb + r;
        const int j = ei[e];        // source
        const int i = ei[NE + e];   // target
        if (t == 0) s_dst[r] = i;
        s_in[r][t]       = g_nf0 [i * ND + t];
        s_in[r][128 + t] = nf_in [i * ND + t];
        s_in[r][256 + t] = g_nf0 [j * ND + t];
        s_in[r][384 + t] = nf_in [j * ND + t];
        s_in[r][512 + t] = g_ef0 [e * ED + t];
        s_in[r][640 + t] = g_ef  [e * ED + t];
    }
    __syncthreads();

    // Phase 1: h = relu([x_i | x_j | efc] @ mew0 + meb0), 64 outputs,
    // split-k: two threads cooperate per output (768 -> 2x384), float4 LDS.
    {
        const int c = t & 63, half = t >> 6;
        const int k0 = half * 384;
        float acc[EPB];
        #pragma unroll
        for (int r = 0; r < EPB; r++) acc[r] = 0.f;
        #pragma unroll 2
        for (int kk = 0; kk < 384; kk += 4) {
            const int k = k0 + kk;
            float4 w4;
            w4.x = mew0[(k + 0) * HH + c];
            w4.y = mew0[(k + 1) * HH + c];
            w4.z = mew0[(k + 2) * HH + c];
            w4.w = mew0[(k + 3) * HH + c];
            #pragma unroll
            for (int r = 0; r < EPB; r++) {
                const float4 v = *(const float4*)&s_in[r][k];
                acc[r] += v.x * w4.x + v.y * w4.y + v.z * w4.z + v.w * w4.w;
            }
        }
        #pragma unroll
        for (int r = 0; r < EPB; r++) s_part[t][r] = acc[r];
    }
    __syncthreads();
    if (t < HH) {
        const float b = meb0[t];
        #pragma unroll
        for (int r = 0; r < EPB; r++)
            s_h[r][t] = fmaxf(s_part[t][r] + s_part[t + 64][r] + b, 0.f);
    }
    __syncthreads();

    // Phase 2: ef_new = relu(h @ mew1 + meb1)
    {
        const float b = meb1[t];
        float a2[EPB];
        #pragma unroll
        for (int r = 0; r < EPB; r++) a2[r] = b;
        #pragma unroll 4
        for (int k = 0; k < HH; k += 4) {
            float4 w4;
            w4.x = mew1[(k + 0) * ED + t];
            w4.y = mew1[(k + 1) * ED + t];
            w4.z = mew1[(k + 2) * ED + t];
            w4.w = mew1[(k + 3) * ED + t];
            #pragma unroll
            for (int r = 0; r < EPB; r++) {
                const float4 v = *(const float4*)&s_h[r][k];
                a2[r] += v.x * w4.x + v.y * w4.y + v.z * w4.z + v.w * w4.w;
            }
        }
        #pragma unroll
        for (int r = 0; r < EPB; r++) {
            const float v = fmaxf(a2[r], 0.f);
            s_ef[r][t] = v;
            g_ef[(eb + r) * ED + t] = v;
        }
    }

    if (!compute_msg) return;
    __syncthreads();

    // Phase 3: msg = relu([x_i | ef_new] @ mnw0 + mnb0); atomic scatter-add.
    {
        const float b = mnb0[t];
        float m[EPB];
        #pragma unroll
        for (int r = 0; r < EPB; r++) m[r] = b;
        #pragma unroll 2
        for (int k = 0; k < 256; k += 4) {
            float4 w4;
            w4.x = mnw0[(k + 0) * ND + t];
            w4.y = mnw0[(k + 1) * ND + t];
            w4.z = mnw0[(k + 2) * ND + t];
            w4.w = mnw0[(k + 3) * ND + t];
            #pragma unroll
            for (int r = 0; r < EPB; r++) {
                const float4 v = *(const float4*)&s_in[r][k];
                m[r] += v.x * w4.x + v.y * w4.y + v.z * w4.z + v.w * w4.w;
            }
        }
        #pragma unroll 2
        for (int k = 0; k < 128; k += 4) {
            float4 w4;
            w4.x = mnw0[(256 + k + 0) * ND + t];
            w4.y = mnw0[(256 + k + 1) * ND + t];
            w4.z = mnw0[(256 + k + 2) * ND + t];
            w4.w = mnw0[(256 + k + 3) * ND + t];
            #pragma unroll
            for (int r = 0; r < EPB; r++) {
                const float4 v = *(const float4*)&s_ef[r][k];
                m[r] += v.x * w4.x + v.y * w4.y + v.z * w4.z + v.w * w4.w;
            }
        }
        #pragma unroll
        for (int r = 0; r < EPB; r++)
            atomicAdd(&nf_out[s_dst[r] * ND + t], fmaxf(m[r], 0.f));
    }
}

// ---------------------------------------------------------------------------
// Classifier: out = lin(relu(lin(relu(lin(ef, cw0)), cw1)), cw2)  [E,1]
// ---------------------------------------------------------------------------
__global__ void classify_kernel(float* __restrict__ out,
                                const float* __restrict__ cw0, const float* __restrict__ cb0,
                                const float* __restrict__ cw1, const float* __restrict__ cb1,
                                const float* __restrict__ cw2, const float* __restrict__ cb2)
{
    __shared__ float s_ef[EPB][ED];
    __shared__ float s_h0[EPB][64];
    __shared__ float s_h1[EPB][32];
    const int t = threadIdx.x;
    const int eb = blockIdx.x * EPB;

    #pragma unroll
    for (int r = 0; r < EPB; r++) s_ef[r][t] = g_ef[(eb + r) * ED + t];
    __syncthreads();

    if (t < 64) {
        const float b = cb0[t];
        float a[EPB];
        #pragma unroll
        for (int r = 0; r < EPB; r++) a[r] = b;
        #pragma unroll 4
        for (int k = 0; k < 128; k += 4) {
            float4 w4;
            w4.x = cw0[(k + 0) * 64 + t];
            w4.y = cw0[(k + 1) * 64 + t];
            w4.z = cw0[(k + 2) * 64 + t];
            w4.w = cw0[(k + 3) * 64 + t];
            #pragma unroll
            for (int r = 0; r < EPB; r++) {
                const float4 v = *(const float4*)&s_ef[r][k];
                a[r] += v.x * w4.x + v.y * w4.y + v.z * w4.z + v.w * w4.w;
            }
        }
        #pragma unroll
        for (int r = 0; r < EPB; r++) s_h0[r][t] = fmaxf(a[r], 0.f);
    }
    __syncthreads();

    if (t < 32) {
        const float b = cb1[t];
        float a[EPB];
        #pragma unroll
        for (int r = 0; r < EPB; r++) a[r] = b;
        #pragma unroll 4
        for (int k = 0; k < 64; k += 4) {
            float4 w4;
            w4.x = cw1[(k + 0) * 32 + t];
            w4.y = cw1[(k + 1) * 32 + t];
            w4.z = cw1[(k + 2) * 32 + t];
            w4.w = cw1[(k + 3) * 32 + t];
            #pragma unroll
            for (int r = 0; r < EPB; r++) {
                const float4 v = *(const float4*)&s_h0[r][k];
                a[r] += v.x * w4.x + v.y * w4.y + v.z * w4.z + v.w * w4.w;
            }
        }
        #pragma unroll
        for (int r = 0; r < EPB; r++) s_h1[r][t] = fmaxf(a[r], 0.f);
    }
    __syncthreads();

    if (t < 32) {
        const float w2 = cw2[t];
        #pragma unroll
        for (int r = 0; r < EPB; r++) {
            float v = s_h1[r][t] * w2;
            #pragma unroll
            for (int off = 16; off > 0; off >>= 1)
                v += __shfl_down_sync(0xFFFFFFFFu, v, off);
            if (t == 0) out[eb + r] = v + cb2[0];
        }
    }
}

// ---------------------------------------------------------------------------
extern "C" void kernel_launch(void* const* d_in, const int* in_sizes, int n_in,
                              void* d_out, int out_size)
{
    const float* x    = (const float*)d_in[0];
    const float* ea   = (const float*)d_in[1];
    const int*   ei   = (const int*)  d_in[2];
    const float* new0 = (const float*)d_in[3];
    const float* neb0 = (const float*)d_in[4];
    const float* new1 = (const float*)d_in[5];
    const float* neb1 = (const float*)d_in[6];
    const float* eew0 = (const float*)d_in[7];
    const float* eeb0 = (const float*)d_in[8];
    const float* eew1 = (const float*)d_in[9];
    const float* eeb1 = (const float*)d_in[10];
    const float* mew0 = (const float*)d_in[11];
    const float* meb0 = (const float*)d_in[12];
    const float* mew1 = (const float*)d_in[13];
    const float* meb1 = (const float*)d_in[14];
    const float* mnw0 = (const float*)d_in[15];
    const float* mnb0 = (const float*)d_in[16];
    const float* cw0  = (const float*)d_in[17];
    const float* cb0  = (const float*)d_in[18];
    const float* cw1  = (const float*)d_in[19];
    const float* cb1  = (const float*)d_in[20];
    const float* cw2  = (const float*)d_in[21];
    const float* cb2  = (const float*)d_in[22];
    float* out = (float*)d_out;

    node_embed_kernel<<<NN / EPB, 128>>>(x, new0, neb0, new1, neb1);
    edge_embed_kernel<<<NE / EPB, 128>>>(ea, eew0, eeb0, eew1, eeb1);

    const int zgrid = (NN * ND + 255) / 256;
    // step 0: in nf0, out A
    zero_nf_kernel<<<zgrid, 256>>>(0);
    mpn_step_kernel<<<NE / EPB, 128>>>(ei, mew0, meb0, mew1, meb1, mnw0, mnb0, 0, 1);
    // step 1: in A, out B
    zero_nf_kernel<<<zgrid, 256>>>(1);
    mpn_step_kernel<<<NE / EPB, 128>>>(ei, mew0, meb0, mew1, meb1, mnw0, mnb0, 1, 1);
    // step 2: in B, out A
    zero_nf_kernel<<<zgrid, 256>>>(0);
    mpn_step_kernel<<<NE / EPB, 128>>>(ei, mew0, meb0, mew1, meb1, mnw0, mnb0, 2, 1);
    // step 3: in A; final nf never consumed -> skip message/aggregation
    mpn_step_kernel<<<NE / EPB, 128>>>(ei, mew0, meb0, mew1, meb1, mnw0, mnb0, 3, 0);

    classify_kernel<<<NE / EPB, 128>>>(out, cw0, cb0, cw1, cb1, cw2, cb2);
}

// round 7
// speedup vs baseline: 1.3041x; 1.2157x over previous
#include <cuda_runtime.h>
#include <cuda_bf16.h>

#define NN 20000
#define NE 100000
#define ND 128
#define ED 128
#define EIN 291
#define HH 64
#define EPB 8          // for embed/classify kernels

// mpn_step GEMM config
#define BLK_E 128      // edges per block
#define NTH   256      // threads per block
#define AP    132      // A-tile row stride in floats (16B-aligned, conflict-free)

// Scratch (device globals; no allocation allowed)
__device__ float g_nf0[NN * ND];
__device__ float g_nfA[NN * ND];
__device__ float g_nfB[NN * ND];
__device__ float g_ef0[NE * ED];
__device__ float g_ef [NE * ED];

// ---------------------------------------------------------------------------
// f32x2 packed helpers (Blackwell FFMA2 path — PTX only)
// ---------------------------------------------------------------------------
__device__ __forceinline__ void fma2(unsigned long long& d,
                                     unsigned long long a, unsigned long long b) {
    asm("fma.rn.f32x2 %0, %1, %2, %0;" : "+l"(d) : "l"(a), "l"(b));
}
__device__ __forceinline__ unsigned long long pk2(float lo, float hi) {
    unsigned long long r;
    asm("mov.b64 %0, {%1, %2};" : "=l"(r) : "f"(lo), "f"(hi));
    return r;
}
__device__ __forceinline__ void upk2(float& lo, float& hi, unsigned long long v) {
    asm("mov.b64 {%0, %1}, %2;" : "=f"(lo), "=f"(hi) : "l"(v));
}

// ---------------------------------------------------------------------------
// Node embedding: nf0 = lin(relu(lin(x, new0)), new1)   [N,128]
// ---------------------------------------------------------------------------
__global__ void node_embed_kernel(const float* __restrict__ x,
                                  const float* __restrict__ w0, const float* __restrict__ b0,
                                  const float* __restrict__ w1, const float* __restrict__ b1)
{
    __shared__ float s_x[EPB][ND];
    __shared__ float s_h[EPB][ND];
    const int t = threadIdx.x;
    const int nb = blockIdx.x * EPB;

    #pragma unroll
    for (int r = 0; r < EPB; r++) s_x[r][t] = x[(nb + r) * ND + t];
    __syncthreads();

    float acc[EPB];
    {
        const float b = b0[t];
        #pragma unroll
        for (int r = 0; r < EPB; r++) acc[r] = b;
        #pragma unroll 4
        for (int k = 0; k < ND; k += 4) {
            float4 w4;
            w4.x = w0[(k + 0) * ND + t];
            w4.y = w0[(k + 1) * ND + t];
            w4.z = w0[(k + 2) * ND + t];
            w4.w = w0[(k + 3) * ND + t];
            #pragma unroll
            for (int r = 0; r < EPB; r++) {
                const float4 v = *(const float4*)&s_x[r][k];
                acc[r] += v.x * w4.x + v.y * w4.y + v.z * w4.z + v.w * w4.w;
            }
        }
        #pragma unroll
        for (int r = 0; r < EPB; r++) s_h[r][t] = fmaxf(acc[r], 0.f);
    }
    __syncthreads();
    {
        const float b = b1[t];
        #pragma unroll
        for (int r = 0; r < EPB; r++) acc[r] = b;
        #pragma unroll 4
        for (int k = 0; k < ND; k += 4) {
            float4 w4;
            w4.x = w1[(k + 0) * ND + t];
            w4.y = w1[(k + 1) * ND + t];
            w4.z = w1[(k + 2) * ND + t];
            w4.w = w1[(k + 3) * ND + t];
            #pragma unroll
            for (int r = 0; r < EPB; r++) {
                const float4 v = *(const float4*)&s_h[r][k];
                acc[r] += v.x * w4.x + v.y * w4.y + v.z * w4.z + v.w * w4.w;
            }
        }
        #pragma unroll
        for (int r = 0; r < EPB; r++) g_nf0[(nb + r) * ND + t] = acc[r];
    }
}

// ---------------------------------------------------------------------------
// Edge embedding: ef0 = lin(relu(lin(edge_attr, eew0)), eew1)   [E,128]
// ---------------------------------------------------------------------------
__global__ void edge_embed_kernel(const float* __restrict__ ea,
                                  const float* __restrict__ w0, const float* __restrict__ b0,
                                  const float* __restrict__ w1, const float* __restrict__ b1)
{
    __shared__ float s_in[EPB][EIN + 1];
    __shared__ float s_part[128][EPB + 1];
    __shared__ float s_h[EPB][HH];
    const int t = threadIdx.x;
    const int eb = blockIdx.x * EPB;

    #pragma unroll
    for (int r = 0; r < EPB; r++) {
        const float* row = ea + (size_t)(eb + r) * EIN;
        for (int k = t; k < EIN; k += 128) s_in[r][k] = row[k];
    }
    __syncthreads();

    const int c = t & 63, half = t >> 6;
    const int ks = half ? 146 : 0;
    const int ke = half ? EIN : 146;
    float acc[EPB];
    #pragma unroll
    for (int r = 0; r < EPB; r++) acc[r] = 0.f;
    for (int k = ks; k < ke; k++) {
        const float w = w0[k * HH + c];
        #pragma unroll
        for (int r = 0; r < EPB; r++) acc[r] += s_in[r][k] * w;
    }
    #pragma unroll
    for (int r = 0; r < EPB; r++) s_part[t][r] = acc[r];
    __syncthreads();

    if (t < HH) {
        const float b = b0[t];
        #pragma unroll
        for (int r = 0; r < EPB; r++)
            s_h[r][t] = fmaxf(s_part[t][r] + s_part[t + 64][r] + b, 0.f);
    }
    __syncthreads();

    {
        const float b = b1[t];
        float a2[EPB];
        #pragma unroll
        for (int r = 0; r < EPB; r++) a2[r] = b;
        #pragma unroll 4
        for (int k = 0; k < HH; k += 4) {
            float4 w4;
            w4.x = w1[(k + 0) * ED + t];
            w4.y = w1[(k + 1) * ED + t];
            w4.z = w1[(k + 2) * ED + t];
            w4.w = w1[(k + 3) * ED + t];
            #pragma unroll
            for (int r = 0; r < EPB; r++) {
                const float4 v = *(const float4*)&s_h[r][k];
                a2[r] += v.x * w4.x + v.y * w4.y + v.z * w4.z + v.w * w4.w;
            }
        }
        #pragma unroll
        for (int r = 0; r < EPB; r++) {
            const int e = eb + r;
            g_ef0[e * ED + t] = a2[r];
            g_ef [e * ED + t] = a2[r];
        }
    }
}

// ---------------------------------------------------------------------------
__global__ void zero_nf_kernel(int sel)
{
    float* p = sel ? g_nfB : g_nfA;
    const int i = blockIdx.x * blockDim.x + threadIdx.x;
    if (i < NN * ND) p[i] = 0.f;
}

// ---------------------------------------------------------------------------
// One message-passing step as three register-tiled GEMMs over 128-edge tiles.
//   A tiles gathered (transposed) into smem per 64-k chunk, weights staged in
//   smem, f32x2 packed FMA with edge pairs in the two lanes.
//   phase: 0: nf_in=g_nf0 out A | 1: in A out B | 2: in B out A | 3: in A
// ---------------------------------------------------------------------------
__global__ void __launch_bounds__(NTH)
mpn_step_kernel(const int* __restrict__ ei,
                const float* __restrict__ mew0, const float* __restrict__ meb0,
                const float* __restrict__ mew1, const float* __restrict__ meb1,
                const float* __restrict__ mnw0, const float* __restrict__ mnb0,
                int phase, int compute_msg)
{
    extern __shared__ float smf[];
    float* sA  = smf;                       // [64][AP]
    float* sB  = smf + 64 * AP;             // [64][128] max
    int*   sRi = (int*)(sB + 64 * 128);     // target node per edge
    int*   sRj = sRi + BLK_E;               // source node per edge
    int*   sRe = sRj + BLK_E;               // (clamped) global edge id

    const float* __restrict__ nf_in =
        (phase == 0) ? g_nf0 : ((phase & 1) ? g_nfA : g_nfB);
    float* __restrict__ nf_out = (phase & 1) ? g_nfB : g_nfA;

    const int t  = threadIdx.x;
    const int eb = blockIdx.x * BLK_E;
    const int cg = t & 15;        // col-group
    const int eg = t >> 4;        // edge-group (16 groups x 8 edges)
    const int e0 = eg * 8;
    const int ge = t & 127;       // gather edge
    const int gh = t >> 7;        // gather k-half (0/1)

    if (t < BLK_E) {
        int e = eb + t; if (e > NE - 1) e = NE - 1;
        sRe[t] = e;
        sRj[t] = ei[e];
        sRi[t] = ei[NE + e];
    }

    // ================= Phase 1: h = relu(A768 @ mew0 + meb0), 64 cols ======
    unsigned long long acc1[4][4];
    #pragma unroll
    for (int c = 0; c < 4; c++) {
        const float b = meb0[cg * 4 + c];
        const unsigned long long bp = pk2(b, b);
        #pragma unroll
        for (int p = 0; p < 4; p++) acc1[p][c] = bp;
    }

    for (int ch = 0; ch < 12; ch++) {
        __syncthreads();
        // gather A chunk (rows 64*ch .. +63 of the concat input), transposed
        {
            const int sel = ch >> 2;   // 0: idx=i, 1: idx=j, 2: idx=e
            const int sub = ch & 3;
            const float* src;
            const int* ridx;
            if (sel == 0)      { src = (sub < 2) ? g_nf0 : nf_in; ridx = sRi; }
            else if (sel == 1) { src = (sub < 2) ? g_nf0 : nf_in; ridx = sRj; }
            else               { src = (sub < 2) ? g_ef0 : g_ef;  ridx = sRe; }
            const int koff = (sub & 1) * 64;
            const int row  = ridx[ge];
            const float4* p = (const float4*)(src + (size_t)row * 128 + koff + gh * 32);
            #pragma unroll
            for (int q = 0; q < 8; q++) {
                const float4 v = p[q];
                float* d = sA + (gh * 32 + q * 4) * AP + ge;
                d[0] = v.x; d[AP] = v.y; d[2 * AP] = v.z; d[3 * AP] = v.w;
            }
        }
        // stage B chunk: mew0 rows [64ch..64ch+63] x 64 cols (contiguous)
        {
            const float4* w = (const float4*)(mew0 + ch * 64 * 64);
            float4* d = (float4*)sB;
            for (int x = t; x < 64 * 64 / 4; x += NTH) d[x] = w[x];
        }
        __syncthreads();
        #pragma unroll 4
        for (int kk = 0; kk < 64; kk++) {
            const ulonglong2 a01 = *(const ulonglong2*)(sA + kk * AP + e0);
            const ulonglong2 a23 = *(const ulonglong2*)(sA + kk * AP + e0 + 4);
            const unsigned long long av[4] = {a01.x, a01.y, a23.x, a23.y};
            const float4 w = *(const float4*)(sB + kk * 64 + cg * 4);
            const unsigned long long wv[4] =
                {pk2(w.x, w.x), pk2(w.y, w.y), pk2(w.z, w.z), pk2(w.w, w.w)};
            #pragma unroll
            for (int p = 0; p < 4; p++)
                #pragma unroll
                for (int c = 0; c < 4; c++)
                    fma2(acc1[p][c], av[p], wv[c]);
        }
    }

    // epilogue: relu(h) -> sA transposed [hcol][edge]; stage mew1 full
    __syncthreads();
    #pragma unroll
    for (int p = 0; p < 4; p++)
        #pragma unroll
        for (int c = 0; c < 4; c++) {
            float lo, hi; upk2(lo, hi, acc1[p][c]);
            sA[(cg * 4 + c) * AP + e0 + 2 * p]     = fmaxf(lo, 0.f);
            sA[(cg * 4 + c) * AP + e0 + 2 * p + 1] = fmaxf(hi, 0.f);
        }
    {
        const float4* w = (const float4*)mew1;
        float4* d = (float4*)sB;
        for (int x = t; x < 64 * 128 / 4; x += NTH) d[x] = w[x];
    }
    __syncthreads();

    // ================= Phase 2: ef = relu(h @ mew1 + meb1), 128 cols =======
    unsigned long long acc2[4][8];
    #pragma unroll
    for (int c = 0; c < 8; c++) {
        const float b = meb1[cg * 8 + c];
        const unsigned long long bp = pk2(b, b);
        #pragma unroll
        for (int p = 0; p < 4; p++) acc2[p][c] = bp;
    }
    #pragma unroll 2
    for (int kk = 0; kk < 64; kk++) {
        const ulonglong2 a01 = *(const ulonglong2*)(sA + kk * AP + e0);
        const ulonglong2 a23 = *(const ulonglong2*)(sA + kk * AP + e0 + 4);
        const unsigned long long av[4] = {a01.x, a01.y, a23.x, a23.y};
        const float4 w0 = *(const float4*)(sB + kk * 128 + cg * 8);
        const float4 w1 = *(const float4*)(sB + kk * 128 + cg * 8 + 4);
        const unsigned long long wv[8] =
            {pk2(w0.x, w0.x), pk2(w0.y, w0.y), pk2(w0.z, w0.z), pk2(w0.w, w0.w),
             pk2(w1.x, w1.x), pk2(w1.y, w1.y), pk2(w1.z, w1.z), pk2(w1.w, w1.w)};
        #pragma unroll
        for (int p = 0; p < 4; p++)
            #pragma unroll
            for (int c = 0; c < 8; c++)
                fma2(acc2[p][c], av[p], wv[c]);
    }
    // epilogue: relu + store ef to global (read back by phase 3 / next step)
    #pragma unroll
    for (int p = 0; p < 4; p++) {
        float lo[8], hi[8];
        #pragma unroll
        for (int c = 0; c < 8; c++) {
            upk2(lo[c], hi[c], acc2[p][c]);
            lo[c] = fmaxf(lo[c], 0.f);
            hi[c] = fmaxf(hi[c], 0.f);
        }
        const int el0 = e0 + 2 * p;
        if (eb + el0 < NE) {
            float4* d = (float4*)(g_ef + (size_t)(eb + el0) * 128 + cg * 8);
            d[0] = make_float4(lo[0], lo[1], lo[2], lo[3]);
            d[1] = make_float4(lo[4], lo[5], lo[6], lo[7]);
        }
        if (eb + el0 + 1 < NE) {
            float4* d = (float4*)(g_ef + (size_t)(eb + el0 + 1) * 128 + cg * 8);
            d[0] = make_float4(hi[0], hi[1], hi[2], hi[3]);
            d[1] = make_float4(hi[4], hi[5], hi[6], hi[7]);
        }
    }

    if (!compute_msg) return;

    // ====== Phase 3: msg = relu([x_i | ef] @ mnw0 + mnb0); scatter-add =====
    unsigned long long acc3[4][8];
    #pragma unroll
    for (int c = 0; c < 8; c++) {
        const float b = mnb0[cg * 8 + c];
        const unsigned long long bp = pk2(b, b);
        #pragma unroll
        for (int p = 0; p < 4; p++) acc3[p][c] = bp;
    }
    for (int ch = 0; ch < 6; ch++) {
        __syncthreads();
        {
            const float* src;
            const int* ridx;
            if (ch < 2)      { src = g_nf0; ridx = sRi; }
            else if (ch < 4) { src = nf_in; ridx = sRi; }
            else             { src = g_ef;  ridx = sRe; }
            const int koff = (ch & 1) * 64;
            const int row  = ridx[ge];
            const float4* p = (const float4*)(src + (size_t)row * 128 + koff + gh * 32);
            #pragma unroll
            for (int q = 0; q < 8; q++) {
                const float4 v = p[q];
                float* d = sA + (gh * 32 + q * 4) * AP + ge;
                d[0] = v.x; d[AP] = v.y; d[2 * AP] = v.z; d[3 * AP] = v.w;
            }
        }
        {
            const float4* w = (const float4*)(mnw0 + ch * 64 * 128);
            float4* d = (float4*)sB;
            for (int x = t; x < 64 * 128 / 4; x += NTH) d[x] = w[x];
        }
        __syncthreads();
        #pragma unroll 2
        for (int kk = 0; kk < 64; kk++) {
            const ulonglong2 a01 = *(const ulonglong2*)(sA + kk * AP + e0);
            const ulonglong2 a23 = *(const ulonglong2*)(sA + kk * AP + e0 + 4);
            const unsigned long long av[4] = {a01.x, a01.y, a23.x, a23.y};
            const float4 w0 = *(const float4*)(sB + kk * 128 + cg * 8);
            const float4 w1 = *(const float4*)(sB + kk * 128 + cg * 8 + 4);
            const unsigned long long wv[8] =
                {pk2(w0.x, w0.x), pk2(w0.y, w0.y), pk2(w0.z, w0.z), pk2(w0.w, w0.w),
                 pk2(w1.x, w1.x), pk2(w1.y, w1.y), pk2(w1.z, w1.z), pk2(w1.w, w1.w)};
            #pragma unroll
            for (int p = 0; p < 4; p++)
                #pragma unroll
                for (int c = 0; c < 8; c++)
                    fma2(acc3[p][c], av[p], wv[c]);
        }
    }
    // epilogue: relu + atomic scatter-add to nf_out
    #pragma unroll
    for (int p = 0; p < 4; p++) {
        float lo[8], hi[8];
        #pragma unroll
        for (int c = 0; c < 8; c++) {
            upk2(lo[c], hi[c], acc3[p][c]);
            lo[c] = fmaxf(lo[c], 0.f);
            hi[c] = fmaxf(hi[c], 0.f);
        }
        const int el0 = e0 + 2 * p;
        if (eb + el0 < NE) {
            float* dst = nf_out + (size_t)sRi[el0] * 128 + cg * 8;
            #pragma unroll
            for (int c = 0; c < 8; c++) atomicAdd(dst + c, lo[c]);
        }
        if (eb + el0 + 1 < NE) {
            float* dst = nf_out + (size_t)sRi[el0 + 1] * 128 + cg * 8;
            #pragma unroll
            for (int c = 0; c < 8; c++) atomicAdd(dst + c, hi[c]);
        }
    }
}

// ---------------------------------------------------------------------------
// Classifier: out = lin(relu(lin(relu(lin(ef, cw0)), cw1)), cw2)  [E,1]
// ---------------------------------------------------------------------------
__global__ void classify_kernel(float* __restrict__ out,
                                const float* __restrict__ cw0, const float* __restrict__ cb0,
                                const float* __restrict__ cw1, const float* __restrict__ cb1,
                                const float* __restrict__ cw2, const float* __restrict__ cb2)
{
    __shared__ float s_ef[EPB][ED];
    __shared__ float s_h0[EPB][64];
    __shared__ float s_h1[EPB][32];
    const int t = threadIdx.x;
    const int eb = blockIdx.x * EPB;

    #pragma unroll
    for (int r = 0; r < EPB; r++) s_ef[r][t] = g_ef[(eb + r) * ED + t];
    __syncthreads();

    if (t < 64) {
        const float b = cb0[t];
        float a[EPB];
        #pragma unroll
        for (int r = 0; r < EPB; r++) a[r] = b;
        #pragma unroll 4
        for (int k = 0; k < 128; k += 4) {
            float4 w4;
            w4.x = cw0[(k + 0) * 64 + t];
            w4.y = cw0[(k + 1) * 64 + t];
            w4.z = cw0[(k + 2) * 64 + t];
            w4.w = cw0[(k + 3) * 64 + t];
            #pragma unroll
            for (int r = 0; r < EPB; r++) {
                const float4 v = *(const float4*)&s_ef[r][k];
                a[r] += v.x * w4.x + v.y * w4.y + v.z * w4.z + v.w * w4.w;
            }
        }
        #pragma unroll
        for (int r = 0; r < EPB; r++) s_h0[r][t] = fmaxf(a[r], 0.f);
    }
    __syncthreads();

    if (t < 32) {
        const float b = cb1[t];
        float a[EPB];
        #pragma unroll
        for (int r = 0; r < EPB; r++) a[r] = b;
        #pragma unroll 4
        for (int k = 0; k < 64; k += 4) {
            float4 w4;
            w4.x = cw1[(k + 0) * 32 + t];
            w4.y = cw1[(k + 1) * 32 + t];
            w4.z = cw1[(k + 2) * 32 + t];
            w4.w = cw1[(k + 3) * 32 + t];
            #pragma unroll
            for (int r = 0; r < EPB; r++) {
                const float4 v = *(const float4*)&s_h0[r][k];
                a[r] += v.x * w4.x + v.y * w4.y + v.z * w4.z + v.w * w4.w;
            }
        }
        #pragma unroll
        for (int r = 0; r < EPB; r++) s_h1[r][t] = fmaxf(a[r], 0.f);
    }
    __syncthreads();

    if (t < 32) {
        const float w2 = cw2[t];
        #pragma unroll
        for (int r = 0; r < EPB; r++) {
            float v = s_h1[r][t] * w2;
            #pragma unroll
            for (int off = 16; off > 0; off >>= 1)
                v += __shfl_down_sync(0xFFFFFFFFu, v, off);
            if (t == 0) out[eb + r] = v + cb2[0];
        }
    }
}

// ---------------------------------------------------------------------------
extern "C" void kernel_launch(void* const* d_in, const int* in_sizes, int n_in,
                              void* d_out, int out_size)
{
    const float* x    = (const float*)d_in[0];
    const float* ea   = (const float*)d_in[1];
    const int*   ei   = (const int*)  d_in[2];
    const float* new0 = (const float*)d_in[3];
    const float* neb0 = (const float*)d_in[4];
    const float* new1 = (const float*)d_in[5];
    const float* neb1 = (const float*)d_in[6];
    const float* eew0 = (const float*)d_in[7];
    const float* eeb0 = (const float*)d_in[8];
    const float* eew1 = (const float*)d_in[9];
    const float* eeb1 = (const float*)d_in[10];
    const float* mew0 = (const float*)d_in[11];
    const float* meb0 = (const float*)d_in[12];
    const float* mew1 = (const float*)d_in[13];
    const float* meb1 = (const float*)d_in[14];
    const float* mnw0 = (const float*)d_in[15];
    const float* mnb0 = (const float*)d_in[16];
    const float* cw0  = (const float*)d_in[17];
    const float* cb0  = (const float*)d_in[18];
    const float* cw1  = (const float*)d_in[19];
    const float* cb1  = (const float*)d_in[20];
    const float* cw2  = (const float*)d_in[21];
    const float* cb2  = (const float*)d_in[22];
    float* out = (float*)d_out;

    const int SMEM_BYTES = (64 * AP + 64 * 128) * 4 + 3 * BLK_E * 4;
    cudaFuncSetAttribute(mpn_step_kernel,
                         cudaFuncAttributeMaxDynamicSharedMemorySize, SMEM_BYTES);

    node_embed_kernel<<<NN / EPB, 128>>>(x, new0, neb0, new1, neb1);
    edge_embed_kernel<<<NE / EPB, 128>>>(ea, eew0, eeb0, eew1, eeb1);

    const int zgrid = (NN * ND + 255) / 256;
    const int mgrid = (NE + BLK_E - 1) / BLK_E;

    // step 0: in nf0, out A
    zero_nf_kernel<<<zgrid, 256>>>(0);
    mpn_step_kernel<<<mgrid, NTH, SMEM_BYTES>>>(ei, mew0, meb0, mew1, meb1, mnw0, mnb0, 0, 1);
    // step 1: in A, out B
    zero_nf_kernel<<<zgrid, 256>>>(1);
    mpn_step_kernel<<<mgrid, NTH, SMEM_BYTES>>>(ei, mew0, meb0, mew1, meb1, mnw0, mnb0, 1, 1);
    // step 2: in B, out A
    zero_nf_kernel<<<zgrid, 256>>>(0);
    mpn_step_kernel<<<mgrid, NTH, SMEM_BYTES>>>(ei, mew0, meb0, mew1, meb1, mnw0, mnb0, 2, 1);
    // step 3: in A; final nf never consumed -> skip message/aggregation
    mpn_step_kernel<<<mgrid, NTH, SMEM_BYTES>>>(ei, mew0, meb0, mew1, meb1, mnw0, mnb0, 3, 0);

    classify_kernel<<<NE / EPB, 128>>>(out, cw0, cb0, cw1, cb1, cw2, cb2);
}